// round 2
// baseline (speedup 1.0000x reference)
#include <cuda_runtime.h>

// Problem shape (fixed per reference setup_inputs)
#define BB 8
#define CC 256
#define HH 80
#define WW 80
#define HW (HH * WW)          // 6400
#define GROUPS 32
#define CPG (CC / GROUPS)     // 8
#define TOTAL (BB * CC * HW)  // 13,107,200

// Scratch (allocation-free rule: __device__ globals)
__device__ float g_h1[TOTAL];
__device__ float g_h2[TOTAL];
__device__ float g_gatebuf[BB * HW];
__device__ float g_mean[2 * BB * GROUPS];
__device__ float g_rstd[2 * BB * GROUPS];

// ---------------- conv 3x3, pad 1, 256->256, fp32 direct ----------------
// Block tile: 64 out-channels x (8 rows x 16 cols) pixels, 256 threads.
// Thread micro-tile: 4 consecutive co x 8 rows (one pixel column).
#define CO_TILE 64
#define TH 8
#define TW 16
#define CICH 16

__global__ __launch_bounds__(256)
void conv3x3_kernel(const float* __restrict__ in, const float* __restrict__ w,
                    float* __restrict__ out)
{
    __shared__ float xs[CICH][TH + 2][TW + 2];     // 16*10*18*4 = 11,520 B
    __shared__ float ws[CICH][9][CO_TILE];         // 16*9*64*4  = 36,864 B

    const int bx = blockIdx.x;            // 0..4   (W tiles)
    const int by = blockIdx.y;            // 0..9   (H tiles)
    const int bz = blockIdx.z;            // 0..31  (b*4 + co-tile)
    const int b   = bz >> 2;
    const int co0 = (bz & 3) * CO_TILE;

    const int tid = threadIdx.x;
    const int pxc = tid & 15;             // pixel column within tile
    const int cog = tid >> 4;             // 0..15 -> co = co0 + cog*4 + k

    float acc[4][8];
#pragma unroll
    for (int k = 0; k < 4; k++)
#pragma unroll
        for (int j = 0; j < 8; j++) acc[k][j] = 0.0f;

    const int gy0 = by * TH - 1;
    const int gx0 = bx * TW - 1;

    for (int ci0 = 0; ci0 < CC; ci0 += CICH) {
        __syncthreads();
        // fill x halo tile: 16ci x 10 x 18
        for (int idx = tid; idx < CICH * (TH + 2) * (TW + 2); idx += 256) {
            int c  = idx % (TW + 2);
            int r  = (idx / (TW + 2)) % (TH + 2);
            int ci = idx / ((TW + 2) * (TH + 2));
            int gy = gy0 + r, gx = gx0 + c;
            float v = 0.0f;
            if (gy >= 0 && gy < HH && gx >= 0 && gx < WW)
                v = in[((size_t)(b * CC + ci0 + ci) * HH + gy) * WW + gx];
            xs[ci][r][c] = v;
        }
        // fill weight tile: ws[ci][t][co] = w[co0+co][ci0+ci][t]
        for (int idx = tid; idx < CO_TILE * CICH * 9; idx += 256) {
            int t  = idx % 9;
            int ci = (idx / 9) % CICH;
            int co = idx / (9 * CICH);
            ws[ci][t][co] = w[((size_t)(co0 + co) * CC + ci0 + ci) * 9 + t];
        }
        __syncthreads();

        for (int ci = 0; ci < CICH; ci++) {
#pragma unroll
            for (int t = 0; t < 9; t++) {
                const int kh = t / 3, kw = t % 3;
                float4 wv = *(const float4*)&ws[ci][t][cog * 4];
#pragma unroll
                for (int j = 0; j < 8; j++) {
                    float xv = xs[ci][j + kh][pxc + kw];
                    acc[0][j] = fmaf(wv.x, xv, acc[0][j]);
                    acc[1][j] = fmaf(wv.y, xv, acc[1][j]);
                    acc[2][j] = fmaf(wv.z, xv, acc[2][j]);
                    acc[3][j] = fmaf(wv.w, xv, acc[3][j]);
                }
            }
        }
    }

#pragma unroll
    for (int k = 0; k < 4; k++) {
        const int co = co0 + cog * 4 + k;
#pragma unroll
        for (int j = 0; j < 8; j++) {
            const int gy = by * TH + j;
            const int gx = bx * TW + pxc;
            out[((size_t)(b * CC + co) * HH + gy) * WW + gx] = acc[k][j];
        }
    }
}

// ---------------- GroupNorm statistics: one block per (b, group) ----------------
__global__ __launch_bounds__(256)
void gn_stats_kernel(const float* __restrict__ in, float* __restrict__ mean,
                     float* __restrict__ rstd)
{
    const int bg = blockIdx.x;                 // 0..255 == b*32+g, contiguous slab
    const float* p = in + (size_t)bg * (CPG * HW);
    const int tid = threadIdx.x;

    float s = 0.0f, ss = 0.0f;
    for (int i = tid; i < CPG * HW; i += 256) {
        float v = p[i];
        s += v;
        ss = fmaf(v, v, ss);
    }
    __shared__ float sb0[8], sb1[8];
#pragma unroll
    for (int o = 16; o; o >>= 1) {
        s  += __shfl_down_sync(0xffffffffu, s, o);
        ss += __shfl_down_sync(0xffffffffu, ss, o);
    }
    if ((tid & 31) == 0) { sb0[tid >> 5] = s; sb1[tid >> 5] = ss; }
    __syncthreads();
    if (tid == 0) {
        s = 0.0f; ss = 0.0f;
#pragma unroll
        for (int i = 0; i < 8; i++) { s += sb0[i]; ss += sb1[i]; }
        const float inv_n = 1.0f / (float)(CPG * HW);
        float m   = s * inv_n;
        float var = ss * inv_n - m * m;
        mean[bg] = m;
        rstd[bg] = rsqrtf(var + 1e-5f);
    }
}

// ---------------- apply GN + ReLU (in place), float4 ----------------
__global__ __launch_bounds__(256)
void gn_apply_relu_kernel(float* __restrict__ h, const float* __restrict__ mean,
                          const float* __restrict__ rstd,
                          const float* __restrict__ w, const float* __restrict__ bias)
{
    int idx = blockIdx.x * blockDim.x + threadIdx.x;   // float4 index
    if (idx >= TOTAL / 4) return;
    const int c  = (idx / (HW / 4)) % CC;
    const int b  = idx / ((HW / 4) * CC);
    const int bg = b * GROUPS + c / CPG;
    const float sc = rstd[bg] * w[c];
    const float sb = fmaf(-mean[bg], sc, bias[c]);
    float4 v = ((float4*)h)[idx];
    v.x = fmaxf(fmaf(v.x, sc, sb), 0.0f);
    v.y = fmaxf(fmaf(v.y, sc, sb), 0.0f);
    v.z = fmaxf(fmaf(v.z, sc, sb), 0.0f);
    v.w = fmaxf(fmaf(v.w, sc, sb), 0.0f);
    ((float4*)h)[idx] = v;
}

// ---------------- spatial gate: g[b,p] = max(tanh(sum_c x*gw + gb), 0) ----------------
__global__ __launch_bounds__(256)
void gate_kernel(const float* __restrict__ x, const float* __restrict__ gw,
                 const float* __restrict__ gb, float* __restrict__ gate)
{
    __shared__ float wsm[CC];
    const int tid = threadIdx.x;
    wsm[tid] = gw[tid];                      // blockDim == CC == 256
    __syncthreads();
    const int p  = blockIdx.x * 256 + tid;   // 0..BB*HW-1
    const int b  = p / HW;
    const int pp = p % HW;
    const float* xb = x + (size_t)b * CC * HW + pp;
    float s = gb[0];
#pragma unroll 8
    for (int c = 0; c < CC; c++) s = fmaf(xb[(size_t)c * HW], wsm[c], s);
    gate[p] = fmaxf(tanhf(s), 0.0f);
}

// ---------------- final: out = relu(gn2(h2)*gate + x), float4 ----------------
__global__ __launch_bounds__(256)
void final_kernel(const float* __restrict__ h2, const float* __restrict__ mean,
                  const float* __restrict__ rstd, const float* __restrict__ w,
                  const float* __restrict__ bias, const float* __restrict__ gate,
                  const float* __restrict__ x, float* __restrict__ out)
{
    int idx = blockIdx.x * blockDim.x + threadIdx.x;   // float4 index
    if (idx >= TOTAL / 4) return;
    const int c  = (idx / (HW / 4)) % CC;
    const int b  = idx / ((HW / 4) * CC);
    const int bg = b * GROUPS + c / CPG;
    const float sc = rstd[bg] * w[c];
    const float sb = fmaf(-mean[bg], sc, bias[c]);

    const int p4 = idx % (HW / 4);
    const float4 g4 = ((const float4*)(gate + (size_t)b * HW))[p4];
    float4 hv = ((const float4*)h2)[idx];
    float4 xv = ((const float4*)x)[idx];
    float4 o;
    o.x = fmaxf(fmaf(fmaf(hv.x, sc, sb), g4.x, xv.x), 0.0f);
    o.y = fmaxf(fmaf(fmaf(hv.y, sc, sb), g4.y, xv.y), 0.0f);
    o.z = fmaxf(fmaf(fmaf(hv.z, sc, sb), g4.z, xv.z), 0.0f);
    o.w = fmaxf(fmaf(fmaf(hv.w, sc, sb), g4.w, xv.w), 0.0f);
    ((float4*)out)[idx] = o;
}

// ---------------- launch ----------------
extern "C" void kernel_launch(void* const* d_in, const int* in_sizes, int n_in,
                              void* d_out, int out_size)
{
    const float* x    = (const float*)d_in[0];
    const float* w1   = (const float*)d_in[1];
    const float* gn1w = (const float*)d_in[2];
    const float* gn1b = (const float*)d_in[3];
    const float* w2   = (const float*)d_in[4];
    const float* gn2w = (const float*)d_in[5];
    const float* gn2b = (const float*)d_in[6];
    const float* gw   = (const float*)d_in[7];
    const float* gb   = (const float*)d_in[8];
    float* out = (float*)d_out;

    float *h1, *h2, *gatebuf, *meanb, *rstdb;
    cudaGetSymbolAddress((void**)&h1,      g_h1);
    cudaGetSymbolAddress((void**)&h2,      g_h2);
    cudaGetSymbolAddress((void**)&gatebuf, g_gatebuf);
    cudaGetSymbolAddress((void**)&meanb,   g_mean);
    cudaGetSymbolAddress((void**)&rstdb,   g_rstd);

    dim3 cgrid(WW / TW, HH / TH, BB * (CC / CO_TILE));   // 5 x 10 x 32
    const int ew_blocks = (TOTAL / 4 + 255) / 256;       // 12800

    // conv1 -> GN1 stats -> GN1+ReLU
    conv3x3_kernel<<<cgrid, 256>>>(x, w1, h1);
    gn_stats_kernel<<<BB * GROUPS, 256>>>(h1, meanb, rstdb);
    gn_apply_relu_kernel<<<ew_blocks, 256>>>(h1, meanb, rstdb, gn1w, gn1b);
    // conv2 -> GN2 stats
    conv3x3_kernel<<<cgrid, 256>>>(h1, w2, h2);
    gn_stats_kernel<<<BB * GROUPS, 256>>>(h2, meanb + BB * GROUPS, rstdb + BB * GROUPS);
    // gate from original x
    gate_kernel<<<(BB * HW) / 256, 256>>>(x, gw, gb, gatebuf);
    // epilogue: GN2 apply * gate + residual, ReLU
    final_kernel<<<ew_blocks, 256>>>(h2, meanb + BB * GROUPS, rstdb + BB * GROUPS,
                                     gn2w, gn2b, gatebuf, x, out);
}

// round 8
// speedup vs baseline: 3.6280x; 3.6280x over previous
#include <cuda_runtime.h>
#include <cstdint>

// ---------------- problem constants ----------------
#define BB 8
#define CC 256
#define HHW 6400          // 80*80
#define GROUPS 32
#define CPG 8
#define TOTAL (BB*CC*HHW) // 13,107,200
#define PW 82
#define PHW (PW*PW)       // 6724
#define KTOT (CC*9)       // 2304
#define KC 32
#define NCHUNK (KTOT/KC)  // 72
#define K8TOT (KTOT/8)    // 288

// ---------------- scratch (__device__ globals; no allocation) ----------------
__device__ float  g_pad[(size_t)BB*CC*PHW];    // padded, tf32-rounded conv input
__device__ float2 g_wt2[(size_t)CC/8 * K8TOT * 32]; // weights in B-fragment order
__device__ float  g_h[(size_t)TOTAL];          // raw conv output (reused conv1/conv2)
__device__ float  g_gate[BB*HHW];
__device__ float  g_mean[BB*GROUPS];
__device__ float  g_rstd[BB*GROUPS];

// ---------------- helpers ----------------
__device__ __forceinline__ float f2tf32(float v){
    uint32_t r; asm("cvt.rna.tf32.f32 %0, %1;" : "=r"(r) : "f"(v));
    return __uint_as_float(r);
}

__device__ __forceinline__ void mma_tf32(float* d, const uint32_t* a, const uint32_t* b){
    asm volatile(
        "mma.sync.aligned.m16n8k8.row.col.f32.tf32.tf32.f32 "
        "{%0,%1,%2,%3}, {%4,%5,%6,%7}, {%8,%9}, {%0,%1,%2,%3};"
        : "+f"(d[0]), "+f"(d[1]), "+f"(d[2]), "+f"(d[3])
        : "r"(a[0]), "r"(a[1]), "r"(a[2]), "r"(a[3]), "r"(b[0]), "r"(b[1]));
}

// k -> offset within one (b) image of g_pad: ci*PHW + dy*PW + dx
__device__ __forceinline__ int koff_of(int k){
    int ci = k / 9, t = k - ci * 9;
    int dy = t / 3, dx = t - dy * 3;
    return ci * PHW + dy * PW + dx;
}

// ---------------- prep kernels ----------------
// weights -> B-fragment order: entry idx2 = (cot*K8TOT + k8)*32 + lane
//   b0 = W[cot*8 + lane/4][k8*8 + lane%4], b1 = same with k+4   (tf32-rounded)
__global__ __launch_bounds__(256)
void prep_w_kernel(const float* __restrict__ w, float2* __restrict__ wt2)
{
    int i = blockIdx.x * 256 + threadIdx.x;
    if (i >= (CC/8) * K8TOT * 32) return;
    int lane = i & 31;
    int k8   = (i >> 5) % K8TOT;
    int cot  = i / (32 * K8TOT);
    int co = cot * 8 + (lane >> 2);
    int k0 = k8 * 8 + (lane & 3);
    int ci0 = k0 / 9, t0 = k0 - ci0 * 9;
    int k1 = k0 + 4;
    int ci1 = k1 / 9, t1 = k1 - ci1 * 9;
    float2 v;
    v.x = f2tf32(w[((size_t)co * CC + ci0) * 9 + t0]);
    v.y = f2tf32(w[((size_t)co * CC + ci1) * 9 + t1]);
    wt2[i] = v;
}

// pad x (tf32) into g_pad
__global__ __launch_bounds__(256)
void pad_x_kernel(const float* __restrict__ x, float* __restrict__ pad)
{
    int i = blockIdx.x * 256 + threadIdx.x;
    if (i >= BB * CC * PHW) return;
    int bc = i / PHW, rr = i - bc * PHW;
    int r = rr / PW, c = rr - r * PW;
    float v = 0.0f;
    if (r >= 1 && r <= 80 && c >= 1 && c <= 80)
        v = x[(size_t)bc * HHW + (r - 1) * 80 + (c - 1)];
    pad[i] = f2tf32(v);
}

// pad h with GN affine + ReLU + tf32
__global__ __launch_bounds__(256)
void pad_h_kernel(const float* __restrict__ h, const float* __restrict__ mean,
                  const float* __restrict__ rstd, const float* __restrict__ gw,
                  const float* __restrict__ gb, float* __restrict__ pad)
{
    int i = blockIdx.x * 256 + threadIdx.x;
    if (i >= BB * CC * PHW) return;
    int bc = i / PHW, rr = i - bc * PHW;
    int r = rr / PW, c = rr - r * PW;
    float v = 0.0f;
    if (r >= 1 && r <= 80 && c >= 1 && c <= 80) {
        int ch = bc % CC, b = bc / CC;
        int bg = b * GROUPS + ch / CPG;
        float sc = rstd[bg] * gw[ch];
        float sb = fmaf(-mean[bg], sc, gb[ch]);
        v = fmaxf(fmaf(h[(size_t)bc * HHW + (r - 1) * 80 + (c - 1)], sc, sb), 0.0f);
    }
    pad[i] = f2tf32(v);
}

// ---------------- HMMA tf32 implicit-GEMM conv ----------------
// CTA: 256 thr = 8 warps (2M x 4N). CTA tile 128px x 128co. K chunks of 32.
// smem (dynamic 64KB): A0[16K] A1[16K] B0[16K] B1[16K], fragment-ordered.
__global__ __launch_bounds__(256)
void conv_mma_kernel(const float* __restrict__ pad, const float2* __restrict__ wt2,
                     float* __restrict__ out)
{
    extern __shared__ char dsm[];
    float4* Abuf[2] = { (float4*)dsm, (float4*)dsm + 1024 };
    float2* Bbuf[2] = { (float2*)(dsm + 32768), (float2*)(dsm + 32768) + 2048 };

    const int tid  = threadIdx.x;
    const int lane = tid & 31;
    const int warp = tid >> 5;
    const int mw = warp >> 2;      // 0..1
    const int nw = warp & 3;       // 0..3

    const int px0 = blockIdx.x * 128;
    const int co0 = blockIdx.y * 128;
    const int b   = px0 / HHW;
    const int pxbase = px0 - b * HHW;
    const float* Abase = pad + (size_t)b * CC * PHW;

    // producer-fixed decomposition (invariant over the 4/8 iterations)
    const int ktP   = (tid >> 5) & 3;      // kt for both A and B producer roles
    const int rowin = lane >> 2;           // px sub-row
    const int klane = lane & 3;
    const int mt0   = tid >> 7;            // A: mt = mt0 + 2i
    const int nt0   = tid >> 7;            // B: nt = nt0 + 2i

    // precompute the 8 pixel base offsets this thread gathers (mt = mt0+2i, rows +0/+8)
    int pxoff[4][2];
#pragma unroll
    for (int i = 0; i < 4; i++) {
        int mt = mt0 + 2 * i;
#pragma unroll
        for (int h = 0; h < 2; h++) {
            int px = pxbase + mt * 16 + rowin + h * 8;
            int y = px / 80, xx = px - y * 80;
            pxoff[i][h] = y * PW + xx;
        }
    }

    float acc[4][4][4];
#pragma unroll
    for (int mi = 0; mi < 4; mi++)
#pragma unroll
        for (int ni = 0; ni < 4; ni++)
#pragma unroll
            for (int q = 0; q < 4; q++) acc[mi][ni][q] = 0.0f;

    // ---- prologue: produce chunk 0 into buffer 0 ----
    {
        int kA0 = 0 * KC + ktP * 8 + klane;
        int ko0 = koff_of(kA0), ko1 = koff_of(kA0 + 4);
#pragma unroll
        for (int i = 0; i < 4; i++) {
            float4 v;
            v.x = Abase[pxoff[i][0] + ko0];
            v.y = Abase[pxoff[i][1] + ko0];
            v.z = Abase[pxoff[i][0] + ko1];
            v.w = Abase[pxoff[i][1] + ko1];
            Abuf[0][tid + i * 256] = v;
        }
#pragma unroll
        for (int i = 0; i < 8; i++) {
            int nt = nt0 + 2 * i;
            int cot = (co0 >> 3) + nt;
            int k8  = 0 * 4 + ktP;
            Bbuf[0][tid + i * 256] = wt2[((size_t)cot * K8TOT + k8) * 32 + lane];
        }
    }
    __syncthreads();

    float4 pa[4];
    float2 pb[8];

    for (int ch = 0; ch < NCHUNK; ch++) {
        const int cur = ch & 1;

        // ---- issue gathers for next chunk (held in regs across consume) ----
        if (ch + 1 < NCHUNK) {
            int kA0 = (ch + 1) * KC + ktP * 8 + klane;
            int ko0 = koff_of(kA0), ko1 = koff_of(kA0 + 4);
#pragma unroll
            for (int i = 0; i < 4; i++) {
                pa[i].x = Abase[pxoff[i][0] + ko0];
                pa[i].y = Abase[pxoff[i][1] + ko0];
                pa[i].z = Abase[pxoff[i][0] + ko1];
                pa[i].w = Abase[pxoff[i][1] + ko1];
            }
            int k8 = (ch + 1) * 4 + ktP;
#pragma unroll
            for (int i = 0; i < 8; i++) {
                int cot = (co0 >> 3) + nt0 + 2 * i;
                pb[i] = wt2[((size_t)cot * K8TOT + k8) * 32 + lane];
            }
        }

        // ---- consume current chunk: 4 k-steps of 8 ----
        const uint4* As = (const uint4*)Abuf[cur];
        const uint2* Bs = (const uint2*)Bbuf[cur];
#pragma unroll
        for (int kt = 0; kt < 4; kt++) {
            uint4 af[4];
            uint2 bf[4];
#pragma unroll
            for (int mi = 0; mi < 4; mi++) {
                int mt = mw * 4 + mi;
                af[mi] = As[(mt * 4 + kt) * 32 + lane];
            }
#pragma unroll
            for (int ni = 0; ni < 4; ni++) {
                int nt = nw * 4 + ni;
                bf[ni] = Bs[(nt * 4 + kt) * 32 + lane];
            }
#pragma unroll
            for (int mi = 0; mi < 4; mi++)
#pragma unroll
                for (int ni = 0; ni < 4; ni++)
                    mma_tf32(acc[mi][ni], (const uint32_t*)&af[mi], (const uint32_t*)&bf[ni]);
        }

        // ---- store prefetched regs into the other buffer ----
        if (ch + 1 < NCHUNK) {
            const int nxt = cur ^ 1;
#pragma unroll
            for (int i = 0; i < 4; i++) Abuf[nxt][tid + i * 256] = pa[i];
#pragma unroll
            for (int i = 0; i < 8; i++) Bbuf[nxt][tid + i * 256] = pb[i];
        }
        __syncthreads();
    }

    // ---- epilogue: acc -> out[b][co][px] ----
    // frag element map: c0(r,2t) c1(r,2t+1) c2(r+8,2t) c3(r+8,2t+1)
    const int r0 = lane >> 2;
    const int c0 = 2 * (lane & 3);
#pragma unroll
    for (int mi = 0; mi < 4; mi++) {
        int px_r = pxbase + mw * 64 + mi * 16 + r0;
#pragma unroll
        for (int ni = 0; ni < 4; ni++) {
            int co_c = co0 + nw * 32 + ni * 8 + c0;
            float* o0 = out + ((size_t)b * CC + co_c) * HHW;
            o0[px_r]            = acc[mi][ni][0];
            o0[HHW + px_r]      = acc[mi][ni][1];
            o0[px_r + 8]        = acc[mi][ni][2];
            o0[HHW + px_r + 8]  = acc[mi][ni][3];
        }
    }
}

// ---------------- GroupNorm stats: one block per (b, group) ----------------
__global__ __launch_bounds__(256)
void gn_stats_kernel(const float* __restrict__ in, float* __restrict__ mean,
                     float* __restrict__ rstd)
{
    const int bg = blockIdx.x;
    const float* p = in + (size_t)bg * (CPG * HHW);
    const int tid = threadIdx.x;
    float s = 0.0f, ss = 0.0f;
    for (int i = tid; i < CPG * HHW; i += 256) {
        float v = p[i];
        s += v; ss = fmaf(v, v, ss);
    }
    __shared__ float sb0[8], sb1[8];
#pragma unroll
    for (int o = 16; o; o >>= 1) {
        s  += __shfl_down_sync(0xffffffffu, s, o);
        ss += __shfl_down_sync(0xffffffffu, ss, o);
    }
    if ((tid & 31) == 0) { sb0[tid >> 5] = s; sb1[tid >> 5] = ss; }
    __syncthreads();
    if (tid == 0) {
        s = 0.0f; ss = 0.0f;
#pragma unroll
        for (int i = 0; i < 8; i++) { s += sb0[i]; ss += sb1[i]; }
        const float inv_n = 1.0f / (float)(CPG * HHW);
        float m = s * inv_n;
        float var = ss * inv_n - m * m;
        mean[bg] = m;
        rstd[bg] = rsqrtf(var + 1e-5f);
    }
}

// ---------------- spatial gate ----------------
__global__ __launch_bounds__(256)
void gate_kernel(const float* __restrict__ x, const float* __restrict__ gw,
                 const float* __restrict__ gb, float* __restrict__ gate)
{
    __shared__ float wsm[CC];
    const int tid = threadIdx.x;
    wsm[tid] = gw[tid];
    __syncthreads();
    const int p = blockIdx.x * 256 + tid;
    const int b = p / HHW, pp = p - b * HHW;
    const float* xb = x + (size_t)b * CC * HHW + pp;
    float s = gb[0];
#pragma unroll 8
    for (int c = 0; c < CC; c++) s = fmaf(xb[(size_t)c * HHW], wsm[c], s);
    gate[p] = fmaxf(tanhf(s), 0.0f);
}

// ---------------- final: out = relu(gn2(h)*gate + x) ----------------
__global__ __launch_bounds__(256)
void final_kernel(const float* __restrict__ h, const float* __restrict__ mean,
                  const float* __restrict__ rstd, const float* __restrict__ w,
                  const float* __restrict__ bias, const float* __restrict__ gate,
                  const float* __restrict__ x, float* __restrict__ out)
{
    int idx = blockIdx.x * blockDim.x + threadIdx.x;
    if (idx >= TOTAL / 4) return;
    const int c  = (idx / (HHW / 4)) % CC;
    const int b  = idx / ((HHW / 4) * CC);
    const int bg = b * GROUPS + c / CPG;
    const float sc = rstd[bg] * w[c];
    const float sb = fmaf(-mean[bg], sc, bias[c]);
    const int p4 = idx % (HHW / 4);
    const float4 g4 = ((const float4*)(gate + (size_t)b * HHW))[p4];
    float4 hv = ((const float4*)h)[idx];
    float4 xv = ((const float4*)x)[idx];
    float4 o;
    o.x = fmaxf(fmaf(fmaf(hv.x, sc, sb), g4.x, xv.x), 0.0f);
    o.y = fmaxf(fmaf(fmaf(hv.y, sc, sb), g4.y, xv.y), 0.0f);
    o.z = fmaxf(fmaf(fmaf(hv.z, sc, sb), g4.z, xv.z), 0.0f);
    o.w = fmaxf(fmaf(fmaf(hv.w, sc, sb), g4.w, xv.w), 0.0f);
    ((float4*)out)[idx] = o;
}

// ---------------- launch ----------------
extern "C" void kernel_launch(void* const* d_in, const int* in_sizes, int n_in,
                              void* d_out, int out_size)
{
    const float* x    = (const float*)d_in[0];
    const float* w1   = (const float*)d_in[1];
    const float* gn1w = (const float*)d_in[2];
    const float* gn1b = (const float*)d_in[3];
    const float* w2   = (const float*)d_in[4];
    const float* gn2w = (const float*)d_in[5];
    const float* gn2b = (const float*)d_in[6];
    const float* gw   = (const float*)d_in[7];
    const float* gb   = (const float*)d_in[8];
    float* out = (float*)d_out;

    float *padb, *hb, *gateb, *meanb, *rstdb; float2* wtb;
    cudaGetSymbolAddress((void**)&padb,  g_pad);
    cudaGetSymbolAddress((void**)&wtb,   g_wt2);
    cudaGetSymbolAddress((void**)&hb,    g_h);
    cudaGetSymbolAddress((void**)&gateb, g_gate);
    cudaGetSymbolAddress((void**)&meanb, g_mean);
    cudaGetSymbolAddress((void**)&rstdb, g_rstd);

    const int SMEM = 65536;
    cudaFuncSetAttribute(conv_mma_kernel,
                         cudaFuncAttributeMaxDynamicSharedMemorySize, SMEM);

    const int padN  = BB * CC * PHW;
    const int padBl = (padN + 255) / 256;
    const int wN    = (CC / 8) * K8TOT * 32;
    const int wBl   = (wN + 255) / 256;
    const int ewBl  = (TOTAL / 4 + 255) / 256;
    dim3 cgrid(BB * HHW / 128, CC / 128);   // 400 x 2

    // conv1
    pad_x_kernel<<<padBl, 256>>>(x, padb);
    prep_w_kernel<<<wBl, 256>>>(w1, wtb);
    conv_mma_kernel<<<cgrid, 256, SMEM>>>(padb, wtb, hb);
    // GN1 -> padded relu(gn1(h)); prep w2
    gn_stats_kernel<<<BB * GROUPS, 256>>>(hb, meanb, rstdb);
    pad_h_kernel<<<padBl, 256>>>(hb, meanb, rstdb, gn1w, gn1b, padb);
    prep_w_kernel<<<wBl, 256>>>(w2, wtb);
    // conv2 -> GN2 stats
    conv_mma_kernel<<<cgrid, 256, SMEM>>>(padb, wtb, hb);
    gn_stats_kernel<<<BB * GROUPS, 256>>>(hb, meanb, rstdb);
    // gate + fused epilogue
    gate_kernel<<<(BB * HHW) / 256, 256>>>(x, gw, gb, gateb);
    final_kernel<<<ewBl, 256>>>(hb, meanb, rstdb, gn2w, gn2b, gateb, x, out);
}

// round 9
// speedup vs baseline: 3.7274x; 1.0274x over previous
#include <cuda_runtime.h>
#include <cstdint>

// ---------------- problem constants ----------------
#define BB 8
#define CC 256
#define HHW 6400          // 80*80
#define GROUPS 32
#define CPG 8
#define TOTAL (BB*CC*HHW) // 13,107,200
#define PW 82
#define PHW (PW*PW)       // 6724
#define KTOT (CC*9)       // 2304
#define KC 32
#define NCHUNK (KTOT/KC)  // 72
#define K8TOT (KTOT/8)    // 288

// ---------------- scratch (__device__ globals; no allocation) ----------------
__device__ float  g_pad[(size_t)BB*CC*PHW];    // padded, tf32-rounded conv input
__device__ float2 g_wt2[(size_t)CC/8 * K8TOT * 32]; // weights in B-fragment order
__device__ float  g_h[(size_t)TOTAL];          // raw conv output (reused conv1/conv2)
__device__ float  g_gate[BB*HHW];
__device__ float  g_mean[BB*GROUPS];
__device__ float  g_rstd[BB*GROUPS];

// ---------------- helpers ----------------
__device__ __forceinline__ float f2tf32(float v){
    uint32_t r; asm("cvt.rna.tf32.f32 %0, %1;" : "=r"(r) : "f"(v));
    return __uint_as_float(r);
}

__device__ __forceinline__ void mma_tf32(float* d, const uint32_t* a, const uint32_t* b){
    asm volatile(
        "mma.sync.aligned.m16n8k8.row.col.f32.tf32.tf32.f32 "
        "{%0,%1,%2,%3}, {%4,%5,%6,%7}, {%8,%9}, {%0,%1,%2,%3};"
        : "+f"(d[0]), "+f"(d[1]), "+f"(d[2]), "+f"(d[3])
        : "r"(a[0]), "r"(a[1]), "r"(a[2]), "r"(a[3]), "r"(b[0]), "r"(b[1]));
}

// k -> offset within one (b) image of g_pad: ci*PHW + dy*PW + dx
__device__ __forceinline__ int koff_of(int k){
    int ci = k / 9, t = k - ci * 9;
    int dy = t / 3, dx = t - dy * 3;
    return ci * PHW + dy * PW + dx;
}

// ---------------- prep kernels ----------------
// weights -> B-fragment order: entry idx2 = (cot*K8TOT + k8)*32 + lane
//   b0 = W[cot*8 + lane/4][k8*8 + lane%4], b1 = same with k+4   (tf32-rounded)
__global__ __launch_bounds__(256)
void prep_w_kernel(const float* __restrict__ w, float2* __restrict__ wt2)
{
    int i = blockIdx.x * 256 + threadIdx.x;
    if (i >= (CC/8) * K8TOT * 32) return;
    int lane = i & 31;
    int k8   = (i >> 5) % K8TOT;
    int cot  = i / (32 * K8TOT);
    int co = cot * 8 + (lane >> 2);
    int k0 = k8 * 8 + (lane & 3);
    int ci0 = k0 / 9, t0 = k0 - ci0 * 9;
    int k1 = k0 + 4;
    int ci1 = k1 / 9, t1 = k1 - ci1 * 9;
    float2 v;
    v.x = f2tf32(w[((size_t)co * CC + ci0) * 9 + t0]);
    v.y = f2tf32(w[((size_t)co * CC + ci1) * 9 + t1]);
    wt2[i] = v;
}

// pad x (tf32) into g_pad
__global__ __launch_bounds__(256)
void pad_x_kernel(const float* __restrict__ x, float* __restrict__ pad)
{
    int i = blockIdx.x * 256 + threadIdx.x;
    if (i >= BB * CC * PHW) return;
    int bc = i / PHW, rr = i - bc * PHW;
    int r = rr / PW, c = rr - r * PW;
    float v = 0.0f;
    if (r >= 1 && r <= 80 && c >= 1 && c <= 80)
        v = x[(size_t)bc * HHW + (r - 1) * 80 + (c - 1)];
    pad[i] = f2tf32(v);
}

// pad h with GN affine + ReLU + tf32
__global__ __launch_bounds__(256)
void pad_h_kernel(const float* __restrict__ h, const float* __restrict__ mean,
                  const float* __restrict__ rstd, const float* __restrict__ gw,
                  const float* __restrict__ gb, float* __restrict__ pad)
{
    int i = blockIdx.x * 256 + threadIdx.x;
    if (i >= BB * CC * PHW) return;
    int bc = i / PHW, rr = i - bc * PHW;
    int r = rr / PW, c = rr - r * PW;
    float v = 0.0f;
    if (r >= 1 && r <= 80 && c >= 1 && c <= 80) {
        int ch = bc % CC, b = bc / CC;
        int bg = b * GROUPS + ch / CPG;
        float sc = rstd[bg] * gw[ch];
        float sb = fmaf(-mean[bg], sc, gb[ch]);
        v = fmaxf(fmaf(h[(size_t)bc * HHW + (r - 1) * 80 + (c - 1)], sc, sb), 0.0f);
    }
    pad[i] = f2tf32(v);
}

// ---------------- HMMA tf32 implicit-GEMM conv ----------------
// CTA: 256 thr = 8 warps (2M x 4N). CTA tile = 2D pixel tile (16 rows x 8 cols)
// x 128 co. Pixel m (0..127) -> (py = m>>3, px = m&7). K chunks of 32.
// smem: A0/A1 fragment-order (16KB each), B0/B1 fragment-order (8KB each),
// plus a static k->image-offset table.
__global__ __launch_bounds__(256)
void conv_mma_kernel(const float* __restrict__ pad, const float2* __restrict__ wt2,
                     float* __restrict__ out)
{
    extern __shared__ char dsm[];
    float4* Abuf[2] = { (float4*)dsm, (float4*)dsm + 1024 };
    float2* Bbuf[2] = { (float2*)(dsm + 32768), (float2*)(dsm + 32768) + 2048 };
    __shared__ int s_koff[KTOT];

    const int tid  = threadIdx.x;
    const int lane = tid & 31;
    const int warp = tid >> 5;
    const int mw = warp >> 2;      // 0..1 (consumer M-warp)
    const int nw = warp & 3;       // 0..3 (consumer N-warp)

    // k -> padded-image offset table (once)
    for (int i = tid; i < KTOT; i += 256) s_koff[i] = koff_of(i);

    const int PX0 = blockIdx.x * 8;     // 0..72
    const int PY0 = blockIdx.y * 16;    // 0..64
    const int bz  = blockIdx.z;         // b*2 + co-half
    const int b   = bz >> 1;
    const int co0 = (bz & 1) * 128;
    const float* Abase = pad + (size_t)b * CC * PHW;

    // ---- producer role: each thread owns 4 fragment entries ----
    // warp 'we' covers kt = we&3, mt = (we>>2) + 2j (j=0..3)
    const int ktP = warp & 3;           // shared with B producer role
    const int c_  = lane & 3;           // k sub-index within k8 group
    const int r_  = lane >> 2;          // pixel column 0..7
    const int mtb = warp >> 2;          // 0..1
    int rb[4];                          // row-base offsets (sans k) for a0
#pragma unroll
    for (int j = 0; j < 4; j++)
        rb[j] = (PY0 + 2 * (mtb + 2 * j)) * PW + PX0 + r_;

    // B producer params
    const int nt0 = tid >> 7;

    float acc[4][4][4];
#pragma unroll
    for (int mi = 0; mi < 4; mi++)
#pragma unroll
        for (int ni = 0; ni < 4; ni++)
#pragma unroll
            for (int q = 0; q < 4; q++) acc[mi][ni][q] = 0.0f;

    __syncthreads();   // s_koff ready

    // ---- prologue: produce chunk 0 into buffer 0 ----
    {
        int ko  = s_koff[ktP * 8 + c_];
        int ko2 = s_koff[ktP * 8 + c_ + 4];
#pragma unroll
        for (int j = 0; j < 4; j++) {
            int mt = mtb + 2 * j;
            float4 v;
            v.x = Abase[rb[j] + ko];            // A[r   ][k  ]
            v.y = Abase[rb[j] + PW + ko];       // A[r+8 ][k  ]
            v.z = Abase[rb[j] + ko2];           // A[r   ][k+4]
            v.w = Abase[rb[j] + PW + ko2];      // A[r+8 ][k+4]
            Abuf[0][(mt * 4 + ktP) * 32 + lane] = v;
        }
#pragma unroll
        for (int i = 0; i < 8; i++) {
            int cot = (co0 >> 3) + nt0 + 2 * i;
            Bbuf[0][tid + i * 256] = wt2[((size_t)cot * K8TOT + ktP) * 32 + lane];
        }
    }
    __syncthreads();

    float4 pa[4];
    float2 pb[8];

    for (int ch = 0; ch < NCHUNK; ch++) {
        const int cur = ch & 1;

        // ---- issue gathers for next chunk (held in regs across consume) ----
        if (ch + 1 < NCHUNK) {
            int kb  = (ch + 1) * 32 + ktP * 8;
            int ko  = s_koff[kb + c_];
            int ko2 = s_koff[kb + c_ + 4];
#pragma unroll
            for (int j = 0; j < 4; j++) {
                pa[j].x = Abase[rb[j] + ko];
                pa[j].y = Abase[rb[j] + PW + ko];
                pa[j].z = Abase[rb[j] + ko2];
                pa[j].w = Abase[rb[j] + PW + ko2];
            }
            int k8 = (ch + 1) * 4 + ktP;
#pragma unroll
            for (int i = 0; i < 8; i++) {
                int cot = (co0 >> 3) + nt0 + 2 * i;
                pb[i] = wt2[((size_t)cot * K8TOT + k8) * 32 + lane];
            }
        }

        // ---- consume current chunk: 4 k-steps of 8 ----
        const uint4* As = (const uint4*)Abuf[cur];
        const uint2* Bs = (const uint2*)Bbuf[cur];
#pragma unroll
        for (int kt = 0; kt < 4; kt++) {
            uint4 af[4];
            uint2 bf[4];
#pragma unroll
            for (int mi = 0; mi < 4; mi++) {
                int mt = mw * 4 + mi;
                af[mi] = As[(mt * 4 + kt) * 32 + lane];
            }
#pragma unroll
            for (int ni = 0; ni < 4; ni++) {
                int nt = nw * 4 + ni;
                bf[ni] = Bs[(nt * 4 + kt) * 32 + lane];
            }
#pragma unroll
            for (int mi = 0; mi < 4; mi++)
#pragma unroll
                for (int ni = 0; ni < 4; ni++)
                    mma_tf32(acc[mi][ni], (const uint32_t*)&af[mi], (const uint32_t*)&bf[ni]);
        }

        // ---- store prefetched regs into the other buffer ----
        if (ch + 1 < NCHUNK) {
            const int nxt = cur ^ 1;
#pragma unroll
            for (int j = 0; j < 4; j++) {
                int mt = mtb + 2 * j;
                Abuf[nxt][(mt * 4 + ktP) * 32 + lane] = pa[j];
            }
#pragma unroll
            for (int i = 0; i < 8; i++) Bbuf[nxt][tid + i * 256] = pb[i];
        }
        __syncthreads();
    }

    // ---- epilogue: acc -> out[b][co][y][x] ----
    // d-frag: d0=D[r][c], d1=D[r][c+1], d2=D[r+8][c], d3=D[r+8][c+1]
    // m -> (py = m>>3, px = m&7); m = mw*64 + mi*16 + r0 (r0<8 -> py even)
    const int r0 = lane >> 2;
    const int c0 = 2 * (lane & 3);
#pragma unroll
    for (int mi = 0; mi < 4; mi++) {
        int gpy = PY0 + 8 * mw + 2 * mi;
        int gx  = PX0 + r0;
#pragma unroll
        for (int ni = 0; ni < 4; ni++) {
            int co_c = co0 + nw * 32 + ni * 8 + c0;
            float* p = out + ((size_t)b * CC + co_c) * HHW + gpy * 80 + gx;
            p[0]        = acc[mi][ni][0];
            p[HHW]      = acc[mi][ni][1];
            p[80]       = acc[mi][ni][2];
            p[HHW + 80] = acc[mi][ni][3];
        }
    }
}

// ---------------- GroupNorm stats: one block per (b, group), float4 ----------------
__global__ __launch_bounds__(256)
void gn_stats_kernel(const float* __restrict__ in, float* __restrict__ mean,
                     float* __restrict__ rstd)
{
    const int bg = blockIdx.x;
    const float4* p = (const float4*)(in + (size_t)bg * (CPG * HHW));
    const int tid = threadIdx.x;
    float s = 0.0f, ss = 0.0f;
#pragma unroll 4
    for (int i = tid; i < CPG * HHW / 4; i += 256) {
        float4 v = p[i];
        s += v.x + v.y + v.z + v.w;
        ss = fmaf(v.x, v.x, ss); ss = fmaf(v.y, v.y, ss);
        ss = fmaf(v.z, v.z, ss); ss = fmaf(v.w, v.w, ss);
    }
    __shared__ float sb0[8], sb1[8];
#pragma unroll
    for (int o = 16; o; o >>= 1) {
        s  += __shfl_down_sync(0xffffffffu, s, o);
        ss += __shfl_down_sync(0xffffffffu, ss, o);
    }
    if ((tid & 31) == 0) { sb0[tid >> 5] = s; sb1[tid >> 5] = ss; }
    __syncthreads();
    if (tid == 0) {
        s = 0.0f; ss = 0.0f;
#pragma unroll
        for (int i = 0; i < 8; i++) { s += sb0[i]; ss += sb1[i]; }
        const float inv_n = 1.0f / (float)(CPG * HHW);
        float m = s * inv_n;
        float var = ss * inv_n - m * m;
        mean[bg] = m;
        rstd[bg] = rsqrtf(var + 1e-5f);
    }
}

// ---------------- spatial gate ----------------
__global__ __launch_bounds__(256)
void gate_kernel(const float* __restrict__ x, const float* __restrict__ gw,
                 const float* __restrict__ gb, float* __restrict__ gate)
{
    __shared__ float wsm[CC];
    const int tid = threadIdx.x;
    wsm[tid] = gw[tid];
    __syncthreads();
    const int p = blockIdx.x * 256 + tid;
    const int b = p / HHW, pp = p - b * HHW;
    const float* xb = x + (size_t)b * CC * HHW + pp;
    float s = gb[0];
#pragma unroll 8
    for (int c = 0; c < CC; c++) s = fmaf(xb[(size_t)c * HHW], wsm[c], s);
    gate[p] = fmaxf(tanhf(s), 0.0f);
}

// ---------------- final: out = relu(gn2(h)*gate + x) ----------------
__global__ __launch_bounds__(256)
void final_kernel(const float* __restrict__ h, const float* __restrict__ mean,
                  const float* __restrict__ rstd, const float* __restrict__ w,
                  const float* __restrict__ bias, const float* __restrict__ gate,
                  const float* __restrict__ x, float* __restrict__ out)
{
    int idx = blockIdx.x * blockDim.x + threadIdx.x;
    if (idx >= TOTAL / 4) return;
    const int c  = (idx / (HHW / 4)) % CC;
    const int b  = idx / ((HHW / 4) * CC);
    const int bg = b * GROUPS + c / CPG;
    const float sc = rstd[bg] * w[c];
    const float sb = fmaf(-mean[bg], sc, bias[c]);
    const int p4 = idx % (HHW / 4);
    const float4 g4 = ((const float4*)(gate + (size_t)b * HHW))[p4];
    float4 hv = ((const float4*)h)[idx];
    float4 xv = ((const float4*)x)[idx];
    float4 o;
    o.x = fmaxf(fmaf(fmaf(hv.x, sc, sb), g4.x, xv.x), 0.0f);
    o.y = fmaxf(fmaf(fmaf(hv.y, sc, sb), g4.y, xv.y), 0.0f);
    o.z = fmaxf(fmaf(fmaf(hv.z, sc, sb), g4.z, xv.z), 0.0f);
    o.w = fmaxf(fmaf(fmaf(hv.w, sc, sb), g4.w, xv.w), 0.0f);
    ((float4*)out)[idx] = o;
}

// ---------------- launch ----------------
extern "C" void kernel_launch(void* const* d_in, const int* in_sizes, int n_in,
                              void* d_out, int out_size)
{
    const float* x    = (const float*)d_in[0];
    const float* w1   = (const float*)d_in[1];
    const float* gn1w = (const float*)d_in[2];
    const float* gn1b = (const float*)d_in[3];
    const float* w2   = (const float*)d_in[4];
    const float* gn2w = (const float*)d_in[5];
    const float* gn2b = (const float*)d_in[6];
    const float* gw   = (const float*)d_in[7];
    const float* gb   = (const float*)d_in[8];
    float* out = (float*)d_out;

    float *padb, *hb, *gateb, *meanb, *rstdb; float2* wtb;
    cudaGetSymbolAddress((void**)&padb,  g_pad);
    cudaGetSymbolAddress((void**)&wtb,   g_wt2);
    cudaGetSymbolAddress((void**)&hb,    g_h);
    cudaGetSymbolAddress((void**)&gateb, g_gate);
    cudaGetSymbolAddress((void**)&meanb, g_mean);
    cudaGetSymbolAddress((void**)&rstdb, g_rstd);

    const int SMEM = 65536;
    cudaFuncSetAttribute(conv_mma_kernel,
                         cudaFuncAttributeMaxDynamicSharedMemorySize, SMEM);

    const int padN  = BB * CC * PHW;
    const int padBl = (padN + 255) / 256;
    const int wN    = (CC / 8) * K8TOT * 32;
    const int wBl   = (wN + 255) / 256;
    const int ewBl  = (TOTAL / 4 + 255) / 256;
    dim3 cgrid(10, 5, BB * 2);   // px-tiles x py-tiles x (b, co-half)

    // conv1
    pad_x_kernel<<<padBl, 256>>>(x, padb);
    prep_w_kernel<<<wBl, 256>>>(w1, wtb);
    conv_mma_kernel<<<cgrid, 256, SMEM>>>(padb, wtb, hb);
    // GN1 -> padded relu(gn1(h)); prep w2
    gn_stats_kernel<<<BB * GROUPS, 256>>>(hb, meanb, rstdb);
    pad_h_kernel<<<padBl, 256>>>(hb, meanb, rstdb, gn1w, gn1b, padb);
    prep_w_kernel<<<wBl, 256>>>(w2, wtb);
    // conv2 -> GN2 stats
    conv_mma_kernel<<<cgrid, 256, SMEM>>>(padb, wtb, hb);
    gn_stats_kernel<<<BB * GROUPS, 256>>>(hb, meanb, rstdb);
    // gate + fused epilogue
    gate_kernel<<<(BB * HHW) / 256, 256>>>(x, gw, gb, gateb);
    final_kernel<<<ewBl, 256>>>(hb, meanb, rstdb, gn2w, gn2b, gateb, x, out);
}